// round 1
// baseline (speedup 1.0000x reference)
#include <cuda_runtime.h>
#include <cuda_bf16.h>

// Box_diamond: two-layer soft-AND (product) network over 8-wide bins.
// out[b,p] = 1/(1 - log prod_m(1 - y1[m]*W2[p,m]))
// y1[m]    = 1/(1 - log prod_l(1 - x[b, g*32+l*4+j]*W1[p,m,l])),  p = g*4+j
// W1[p,m,l] = sigmoid((l-m)*(m + t2[p] - l))
// W2[p,l]   = sigmoid((l-t0[p])*(t1[p]-l)) * sigmoid((7-t2[p]-l)*l)
//
// Key transform: sum-of-logs -> log-of-product (1 MUFU.LG2 per 8-term product).

#define B_TOT   4096
#define D_TOT   4096
#define P_TOT   512
#define G_TOT   128     // groups of 32 floats per row
#define BLK_B   32
#define BLK_G   8
#define NTHREADS 256

__device__ __forceinline__ float frcp(float v) {
    float r;
    asm("rcp.approx.f32 %0, %1;" : "=f"(r) : "f"(v));
    return r;
}

__device__ __forceinline__ float fsigmoid(float z) {
    // 1/(1+e^-z) -- accuracy of approx exp/rcp is far inside 1e-3 tolerance
    return frcp(1.0f + __expf(-z));
}

__global__ __launch_bounds__(NTHREADS, 4)
void box_diamond_kernel(const float* __restrict__ x,
                        const float* __restrict__ t0,
                        const float* __restrict__ t1,
                        const float* __restrict__ t2,
                        float* __restrict__ out) {
    // SMEM: gate tables (j-vectorized for float4 LDS) + staged x tile
    __shared__ __align__(16) float W1s[BLK_G][8][8][4];   // [g][m][l][j]  8 KB
    __shared__ __align__(16) float W2s[BLK_G][8][4];      // [g][m][j]     1 KB
    __shared__ __align__(16) float xs[BLK_B][260];        // pitch 260 -> conflict-free LDS.128

    const int tid   = threadIdx.x;          // 0..255
    const int b0    = blockIdx.x * BLK_B;   // batch tile base
    const int gblk  = blockIdx.y;           // 0..15, covers g in [gblk*8, gblk*8+8)
    const int pbase = gblk * (BLK_G * 4);   // 32 p per block

    // ---- build W1 (32 p x 8 m x 8 l = 2048 sigmoids, 8 per thread) ----
    #pragma unroll
    for (int it = 0; it < 8; it++) {
        int idx = it * NTHREADS + tid;      // 0..2047
        int pl  = idx >> 6;                 // p_local 0..31
        int rem = idx & 63;
        int m   = rem >> 3;
        int l   = rem & 7;
        float tt2 = t2[pbase + pl];
        float d = (float)(l - m);
        float w = fsigmoid(d * (tt2 - d));
        W1s[pl >> 2][m][l][pl & 3] = w;
    }
    // ---- build W2 (32 p x 8 l = 256, 1 per thread) ----
    {
        int pl = tid >> 3;
        int l  = tid & 7;
        int p  = pbase + pl;
        float lf = (float)l;
        float z1 = (lf - t0[p]) * (t1[p] - lf);
        float z2 = (7.0f - t2[p] - lf) * lf;
        W2s[pl >> 2][l][pl & 3] = fsigmoid(z1) * fsigmoid(z2);
    }
    // ---- stage x tile: 32 rows x 256 cols, fully coalesced float4 loads ----
    #pragma unroll
    for (int it = 0; it < 8; it++) {
        int idx = it * NTHREADS + tid;      // 0..2047 (float4 units)
        int row = idx >> 6;                 // 0..31
        int c4  = idx & 63;                 // 0..63
        float4 v = *reinterpret_cast<const float4*>(
            x + (size_t)(b0 + row) * D_TOT + (size_t)gblk * 256 + c4 * 4);
        *reinterpret_cast<float4*>(&xs[row][c4 * 4]) = v;
    }
    __syncthreads();

    const int tx = tid & 31;   // b_local (warp lanes span b -> broadcast W reads)
    const int ty = tid >> 5;   // g_local

    // x values for this (b, g): 32 floats as 8 float4 (j components)
    float4 xv[8];
    #pragma unroll
    for (int l = 0; l < 8; l++)
        xv[l] = *reinterpret_cast<const float4*>(&xs[tx][ty * 32 + l * 4]);

    float4 p2 = make_float4(1.f, 1.f, 1.f, 1.f);  // layer-2 running product

    #pragma unroll
    for (int m = 0; m < 8; m++) {
        float4 pr = make_float4(1.f, 1.f, 1.f, 1.f);
        #pragma unroll
        for (int l = 0; l < 8; l++) {
            float4 w = *reinterpret_cast<const float4*>(&W1s[ty][m][l][0]);
            pr.x *= fmaf(-xv[l].x, w.x, 1.f);
            pr.y *= fmaf(-xv[l].y, w.y, 1.f);
            pr.z *= fmaf(-xv[l].z, w.z, 1.f);
            pr.w *= fmaf(-xv[l].w, w.w, 1.f);
        }
        // y1_j = 1/(1 - log(pr_j)); then fold into layer-2 product
        float4 w2 = *reinterpret_cast<const float4*>(&W2s[ty][m][0]);
        float y;
        y = frcp(1.f - __logf(pr.x)); p2.x *= fmaf(-y, w2.x, 1.f);
        y = frcp(1.f - __logf(pr.y)); p2.y *= fmaf(-y, w2.y, 1.f);
        y = frcp(1.f - __logf(pr.z)); p2.z *= fmaf(-y, w2.z, 1.f);
        y = frcp(1.f - __logf(pr.w)); p2.w *= fmaf(-y, w2.w, 1.f);
    }

    float4 o;
    o.x = frcp(1.f - __logf(p2.x));
    o.y = frcp(1.f - __logf(p2.y));
    o.z = frcp(1.f - __logf(p2.z));
    o.w = frcp(1.f - __logf(p2.w));

    *reinterpret_cast<float4*>(out + (size_t)(b0 + tx) * P_TOT + pbase + ty * 4) = o;
}

extern "C" void kernel_launch(void* const* d_in, const int* in_sizes, int n_in,
                              void* d_out, int out_size) {
    const float* x  = (const float*)d_in[0];
    const float* t0 = (const float*)d_in[1];
    const float* t1 = (const float*)d_in[2];
    const float* t2 = (const float*)d_in[3];
    float* out = (float*)d_out;

    int B = in_sizes[0] / D_TOT;           // 4096
    dim3 grid(B / BLK_B, G_TOT / BLK_G);   // (128, 16)
    box_diamond_kernel<<<grid, NTHREADS>>>(x, t0, t1, t2, out);
}

// round 2
// speedup vs baseline: 1.0853x; 1.0853x over previous
#include <cuda_runtime.h>
#include <cuda_bf16.h>

// Box_diamond: two-layer soft-AND (product) network over 8-wide bins.
// out[b,p] = 1/(1 - log prod_m( (s_m - W2[p,m]) / s_m ))
// s_m      = 1 - log prod_l(1 - x[b,g*32+l*4+j]*W1[p,m,l]),  p = g*4+j
// Transforms: sum-of-logs -> log-of-product (1 MUFU.LG2 per 8-term product),
// num/den factoring (kills per-m rcp), f32x2 packed FMA (halves fma-pipe issue).

#define D_TOT   4096
#define P_TOT   512
#define BLK_B   32
#define TILES_PER_BLK 2
#define NTHREADS 256

typedef unsigned long long u64;

#define ONE2     0x3F8000003F800000ULL  // {1.0f, 1.0f}
#define NEGLN2_2 0xBF317218BF317218ULL  // {-ln2, -ln2}

__device__ __forceinline__ u64 fma2(u64 a, u64 b, u64 c) {
    u64 d; asm("fma.rn.f32x2 %0, %1, %2, %3;" : "=l"(d) : "l"(a), "l"(b), "l"(c)); return d;
}
__device__ __forceinline__ u64 mul2(u64 a, u64 b) {
    u64 d; asm("mul.rn.f32x2 %0, %1, %2;" : "=l"(d) : "l"(a), "l"(b)); return d;
}
__device__ __forceinline__ u64 add2(u64 a, u64 b) {
    u64 d; asm("add.rn.f32x2 %0, %1, %2;" : "=l"(d) : "l"(a), "l"(b)); return d;
}
__device__ __forceinline__ u64 pack2(float lo, float hi) {
    u64 d; asm("mov.b64 %0, {%1, %2};" : "=l"(d) : "f"(lo), "f"(hi)); return d;
}
__device__ __forceinline__ void unpack2(float& lo, float& hi, u64 v) {
    asm("mov.b64 {%0, %1}, %2;" : "=f"(lo), "=f"(hi) : "l"(v));
}
__device__ __forceinline__ float frcp(float v) {
    float r; asm("rcp.approx.f32 %0, %1;" : "=f"(r) : "f"(v)); return r;
}
__device__ __forceinline__ float fsigmoid(float z) {
    return frcp(1.0f + __expf(-z));
}

__global__ __launch_bounds__(NTHREADS, 4)
void box_diamond_kernel(const float* __restrict__ x,
                        const float* __restrict__ t0,
                        const float* __restrict__ t1,
                        const float* __restrict__ t2,
                        float* __restrict__ out) {
    __shared__ __align__(16) float W1s[8][8][8][4];   // [g][m][l][j]  8 KB
    __shared__ __align__(16) float W2n[8][8][4];      // -W2, [g][m][j] 1 KB
    __shared__ __align__(16) float xs[BLK_B][260];    // pitch -> conflict-free LDS.128

    const int tid   = threadIdx.x;
    const int gblk  = blockIdx.y;
    const int pbase = gblk * 32;

    // ---- build W1 (32 p x 8 m x 8 l sigmoids, 8/thread) ----
    #pragma unroll
    for (int it = 0; it < 8; it++) {
        int idx = it * NTHREADS + tid;
        int pl  = idx >> 6;
        int rem = idx & 63;
        int m   = rem >> 3;
        int l   = rem & 7;
        float tt2 = t2[pbase + pl];
        float d = (float)(l - m);
        W1s[pl >> 2][m][l][pl & 3] = fsigmoid(d * (tt2 - d));
    }
    // ---- build -W2 (32 p x 8 l, 1/thread) ----
    {
        int pl = tid >> 3;
        int l  = tid & 7;
        int p  = pbase + pl;
        float lf = (float)l;
        float z1 = (lf - t0[p]) * (t1[p] - lf);
        float z2 = (7.0f - t2[p] - lf) * lf;
        W2n[pl >> 2][l][pl & 3] = -fsigmoid(z1) * fsigmoid(z2);
    }

    const int tx = tid & 31;   // b_local (lanes span b -> W reads broadcast)
    const int ty = tid >> 5;   // g_local

    #pragma unroll 1
    for (int bt = 0; bt < TILES_PER_BLK; bt++) {
        const int b0 = (blockIdx.x * TILES_PER_BLK + bt) * BLK_B;
        __syncthreads();  // xs safe to overwrite (also orders W build on bt=0)

        // ---- stage x tile: 32 rows x 256 cols, coalesced float4 ----
        #pragma unroll
        for (int it = 0; it < 8; it++) {
            int idx = it * NTHREADS + tid;
            int row = idx >> 6;
            int c4  = idx & 63;
            float4 v = *reinterpret_cast<const float4*>(
                x + (size_t)(b0 + row) * D_TOT + (size_t)gblk * 256 + c4 * 4);
            *reinterpret_cast<float4*>(&xs[row][c4 * 4]) = v;
        }
        __syncthreads();

        // ---- load -x as packed j-pairs ----
        u64 nx[16];
        #pragma unroll
        for (int l = 0; l < 8; l++) {
            float4 v = *reinterpret_cast<const float4*>(&xs[tx][ty * 32 + l * 4]);
            nx[l * 2]     = pack2(-v.x, -v.y);
            nx[l * 2 + 1] = pack2(-v.z, -v.w);
        }

        u64 num0 = ONE2, num1 = ONE2, den0 = ONE2, den1 = ONE2;

        #pragma unroll
        for (int m = 0; m < 8; m++) {
            u64 pr0 = ONE2, pr1 = ONE2;
            #pragma unroll
            for (int l = 0; l < 8; l++) {
                ulonglong2 w = *reinterpret_cast<const ulonglong2*>(&W1s[ty][m][l][0]);
                pr0 = mul2(pr0, fma2(nx[l * 2],     w.x, ONE2));
                pr1 = mul2(pr1, fma2(nx[l * 2 + 1], w.y, ONE2));
            }
            // s = 1 - ln2*lg2(pr)  (packed)
            float a0, a1, a2, a3;
            unpack2(a0, a1, pr0);
            unpack2(a2, a3, pr1);
            u64 lg01 = pack2(__log2f(a0), __log2f(a1));
            u64 lg23 = pack2(__log2f(a2), __log2f(a3));
            u64 s01 = fma2(lg01, NEGLN2_2, ONE2);
            u64 s23 = fma2(lg23, NEGLN2_2, ONE2);
            ulonglong2 w2 = *reinterpret_cast<const ulonglong2*>(&W2n[ty][m][0]);
            num0 = mul2(num0, add2(s01, w2.x));
            num1 = mul2(num1, add2(s23, w2.y));
            den0 = mul2(den0, s01);
            den1 = mul2(den1, s23);
        }

        // ---- epilogue: out = rcp(1 - ln2*(lg2(num) - lg2(den))) ----
        float n0, n1, n2, n3, d0, d1, d2, d3;
        unpack2(n0, n1, num0); unpack2(n2, n3, num1);
        unpack2(d0, d1, den0); unpack2(d2, d3, den1);
        const float LN2 = 0.6931471805599453f;
        float4 o;
        o.x = frcp(fmaf(-LN2, __log2f(n0) - __log2f(d0), 1.0f));
        o.y = frcp(fmaf(-LN2, __log2f(n1) - __log2f(d1), 1.0f));
        o.z = frcp(fmaf(-LN2, __log2f(n2) - __log2f(d2), 1.0f));
        o.w = frcp(fmaf(-LN2, __log2f(n3) - __log2f(d3), 1.0f));

        *reinterpret_cast<float4*>(out + (size_t)(b0 + tx) * P_TOT + pbase + ty * 4) = o;
    }
}

extern "C" void kernel_launch(void* const* d_in, const int* in_sizes, int n_in,
                              void* d_out, int out_size) {
    const float* x  = (const float*)d_in[0];
    const float* t0 = (const float*)d_in[1];
    const float* t1 = (const float*)d_in[2];
    const float* t2 = (const float*)d_in[3];
    float* out = (float*)d_out;

    int B = in_sizes[0] / D_TOT;                               // 4096
    dim3 grid(B / (BLK_B * TILES_PER_BLK), P_TOT / 32);        // (64, 16)
    box_diamond_kernel<<<grid, NTHREADS>>>(x, t0, t1, t2, out);
}